// round 1
// baseline (speedup 1.0000x reference)
#include <cuda_runtime.h>
#include <cstdint>

// CrossLayer: out = alpha(row) * x_row + beta
//   d_j = x_row . w_j  (j=0..2), computed in one pass
//   s0=d0; t1=1+s0; s1=t1*d1+c01; t2=t1+s1; s2=t2*d2+c012; alpha=t2+s2
//   c01=b0.w1, c012=(b0+b1).w2, beta=b0+b1+b2
//
// 512 threads = 16 warps, one row per warp. F=1024 fixed, L=3 fixed.

#define F_DIM 1024
#define NVEC 256          // F/4 float4s per row
#define THREADS 512
#define WARPS 16
#define ROWS_PER_BLOCK 16

__global__ __launch_bounds__(THREADS, 2)
void cross_layer_kernel(const float* __restrict__ x,
                        const float* __restrict__ kernels,
                        const float* __restrict__ bias,
                        float* __restrict__ out,
                        int B)
{
    // Shared: w0,w1,w2 and beta-sum as float4 arrays (16-byte aligned by type)
    __shared__ float4 sw0[NVEC];
    __shared__ float4 sw1[NVEC];
    __shared__ float4 sw2[NVEC];
    __shared__ float4 sbs[NVEC];
    __shared__ float  sred[2 * WARPS];
    __shared__ float  sc01, sc012;

    const int tid = threadIdx.x;
    const int wid = tid >> 5;
    const int lid = tid & 31;

    // ---- Phase 1: stage w/b into shared, accumulate cross-constants ----
    float pc01 = 0.f, pc012 = 0.f;
    float* fw0 = reinterpret_cast<float*>(sw0);
    float* fw1 = reinterpret_cast<float*>(sw1);
    float* fw2 = reinterpret_cast<float*>(sw2);
    float* fbs = reinterpret_cast<float*>(sbs);
    #pragma unroll
    for (int e = tid; e < F_DIM; e += THREADS) {
        float w0 = __ldg(&kernels[e]);
        float w1 = __ldg(&kernels[F_DIM + e]);
        float w2 = __ldg(&kernels[2 * F_DIM + e]);
        float b0 = __ldg(&bias[e]);
        float b1 = __ldg(&bias[F_DIM + e]);
        float b2 = __ldg(&bias[2 * F_DIM + e]);
        fw0[e] = w0;
        fw1[e] = w1;
        fw2[e] = w2;
        fbs[e] = b0 + b1 + b2;
        pc01  = fmaf(b0, w1, pc01);
        pc012 = fmaf(b0 + b1, w2, pc012);
    }
    // block-reduce the two scalars
    #pragma unroll
    for (int off = 16; off; off >>= 1) {
        pc01  += __shfl_xor_sync(0xFFFFFFFFu, pc01,  off);
        pc012 += __shfl_xor_sync(0xFFFFFFFFu, pc012, off);
    }
    if (lid == 0) { sred[wid] = pc01; sred[WARPS + wid] = pc012; }
    __syncthreads();
    if (tid == 0) {
        float a = 0.f, b = 0.f;
        #pragma unroll
        for (int i = 0; i < WARPS; i++) { a += sred[i]; b += sred[WARPS + i]; }
        sc01 = a; sc012 = b;
    }
    __syncthreads();

    // ---- Phase 2: one row per warp ----
    const int row = blockIdx.x * ROWS_PER_BLOCK + wid;
    if (row >= B) return;

    const float4* __restrict__ xr =
        reinterpret_cast<const float4*>(x + (size_t)row * F_DIM);
    float4* __restrict__ orow =
        reinterpret_cast<float4*>(out + (size_t)row * F_DIM);

    float4 xs[8];
    float p0 = 0.f, p1 = 0.f, p2 = 0.f;
    #pragma unroll
    for (int k = 0; k < 8; k++) {
        const int idx = k * 32 + lid;       // coalesced float4 per warp
        float4 xv = xr[idx];
        xs[k] = xv;
        float4 a = sw0[idx];
        float4 b = sw1[idx];
        float4 c = sw2[idx];
        p0 = fmaf(xv.x, a.x, fmaf(xv.y, a.y, fmaf(xv.z, a.z, fmaf(xv.w, a.w, p0))));
        p1 = fmaf(xv.x, b.x, fmaf(xv.y, b.y, fmaf(xv.z, b.z, fmaf(xv.w, b.w, p1))));
        p2 = fmaf(xv.x, c.x, fmaf(xv.y, c.y, fmaf(xv.z, c.z, fmaf(xv.w, c.w, p2))));
    }
    // warp reduction: all lanes end with full sums
    #pragma unroll
    for (int off = 16; off; off >>= 1) {
        p0 += __shfl_xor_sync(0xFFFFFFFFu, p0, off);
        p1 += __shfl_xor_sync(0xFFFFFFFFu, p1, off);
        p2 += __shfl_xor_sync(0xFFFFFFFFu, p2, off);
    }

    const float t1    = 1.f + p0;
    const float s1    = fmaf(t1, p1, sc01);
    const float t2    = t1 + s1;
    const float s2    = fmaf(t2, p2, sc012);
    const float alpha = t2 + s2;

    #pragma unroll
    for (int k = 0; k < 8; k++) {
        const int idx = k * 32 + lid;
        float4 bv = sbs[idx];
        float4 o;
        o.x = fmaf(alpha, xs[k].x, bv.x);
        o.y = fmaf(alpha, xs[k].y, bv.y);
        o.z = fmaf(alpha, xs[k].z, bv.z);
        o.w = fmaf(alpha, xs[k].w, bv.w);
        orow[idx] = o;
    }
}

extern "C" void kernel_launch(void* const* d_in, const int* in_sizes, int n_in,
                              void* d_out, int out_size)
{
    const float* x       = (const float*)d_in[0];
    const float* kernels = (const float*)d_in[1];
    const float* bias    = (const float*)d_in[2];
    float* out           = (float*)d_out;

    const int B = in_sizes[0] / F_DIM;
    const int grid = (B + ROWS_PER_BLOCK - 1) / ROWS_PER_BLOCK;
    cross_layer_kernel<<<grid, THREADS>>>(x, kernels, bias, out, B);
}